// round 5
// baseline (speedup 1.0000x reference)
#include <cuda_runtime.h>
#include <math.h>

// ---------------- problem constants ----------------
#define N_TOK   16384
#define DIN     256
#define DM      1024
#define HD      2048
#define N_EXP   8
#define TOPK    2
#define N_OUT   2
#define NKPAIR  (N_TOK * TOPK)          // 32768 token-expert pairs

// ---------------- GEMM tiling ----------------
#define BM 64
#define BN 64
#define BK 16
#define MAXMT ((NKPAIR / BM) + N_EXP)   // 520: worst-case ragged M tiles

// ---------------- scratch (device globals; no allocation allowed) ----------
__device__ __align__(16) float g_h[(size_t)N_TOK * DM];       // 64 MB: normalized h
__device__ __align__(16) float g_act[(size_t)NKPAIR * HD];    // 256 MB: gelu activations
__device__ __align__(16) float g_pair[(size_t)NKPAIR * DM];   // 128 MB: gated expert outputs
__device__ int   g_cnt[N_EXP];
__device__ int   g_cursor[N_EXP];
__device__ int   g_off[N_EXP];
__device__ int   g_top_idx[N_TOK * TOPK];
__device__ float g_top_gate[N_TOK * TOPK];
__device__ int   g_src_tok[NKPAIR];
__device__ float g_gate_flat[NKPAIR];
__device__ int   g_dst[NKPAIR];

// ---------------- helpers ----------------
__device__ __forceinline__ float block_sum256(float v, float* red) {
    #pragma unroll
    for (int o = 16; o; o >>= 1) v += __shfl_xor_sync(0xffffffffu, v, o);
    __syncthreads();                       // protect red from prior use
    if ((threadIdx.x & 31) == 0) red[threadIdx.x >> 5] = v;
    __syncthreads();
    float s = 0.f;
    #pragma unroll
    for (int i = 0; i < 8; ++i) s += red[i];
    return s;
}

__device__ __forceinline__ float gelu_tanh(float x) {
    // jax.nn.gelu default (approximate=True)
    float x3 = x * x * x;
    float u  = 0.7978845608028654f * (x + 0.044715f * x3);
    return 0.5f * x * (1.0f + tanhf(u));
}

#define GEMM_INNER                                                              \
    _Pragma("unroll")                                                           \
    for (int kk = 0; kk < BK; ++kk) {                                           \
        float4 a = *(const float4*)&As[kk][ty];                                 \
        float4 b = *(const float4*)&Bs[kk][tx];                                 \
        acc[0][0] += a.x*b.x; acc[0][1] += a.x*b.y; acc[0][2] += a.x*b.z; acc[0][3] += a.x*b.w; \
        acc[1][0] += a.y*b.x; acc[1][1] += a.y*b.y; acc[1][2] += a.y*b.z; acc[1][3] += a.y*b.w; \
        acc[2][0] += a.z*b.x; acc[2][1] += a.z*b.y; acc[2][2] += a.z*b.z; acc[2][3] += a.z*b.w; \
        acc[3][0] += a.w*b.x; acc[3][1] += a.w*b.y; acc[3][2] += a.w*b.z; acc[3][3] += a.w*b.w; \
    }

// ---------------- kernels ----------------
__global__ void k_zero() {
    int t = threadIdx.x;
    if (t < N_EXP) { g_cnt[t] = 0; g_cursor[t] = 0; }
}

// h_pre = x @ w_in + b_in   (M=16384, N=1024, K=256), fp32
__global__ void __launch_bounds__(256)
k_gemm_in(const float* __restrict__ X,
          const float* __restrict__ W,
          const float* __restrict__ bias) {
    __shared__ __align__(16) float As[BK][BM];
    __shared__ __align__(16) float Bs[BK][BN];
    __shared__ float bsh[BN];
    int t = threadIdx.x;
    int m0 = blockIdx.x * BM, n0 = blockIdx.y * BN;
    if (t < BN) bsh[t] = bias[n0 + t];
    int la_m = t >> 2,  la_k = (t & 3)  << 2;
    int lb_k = t >> 4,  lb_n = (t & 15) << 2;
    int tx   = (t & 15) << 2, ty = (t >> 4) << 2;
    float acc[4][4] = {};
    for (int k0 = 0; k0 < DIN; k0 += BK) {
        float4 av = *(const float4*)(X + (size_t)(m0 + la_m) * DIN + k0 + la_k);
        As[la_k+0][la_m] = av.x; As[la_k+1][la_m] = av.y;
        As[la_k+2][la_m] = av.z; As[la_k+3][la_m] = av.w;
        *(float4*)&Bs[lb_k][lb_n] =
            *(const float4*)(W + (size_t)(k0 + lb_k) * DM + n0 + lb_n);
        __syncthreads();
        GEMM_INNER
        __syncthreads();
    }
    float4 bv = *(const float4*)&bsh[tx];
    #pragma unroll
    for (int i = 0; i < 4; ++i) {
        float4 o;
        o.x = acc[i][0] + bv.x;
        o.y = acc[i][1] + bv.y;
        o.z = acc[i][2] + bv.z;
        o.w = acc[i][3] + bv.w;
        *(float4*)(g_h + (size_t)(m0 + ty + i) * DM + n0 + tx) = o;
    }
}

// per-token: LN(h_pre) in place; router logits, softmax, top-2, gates, counts
__global__ void __launch_bounds__(256)
k_ln_router(const float* __restrict__ gw,
            const float* __restrict__ gb,
            const float* __restrict__ wg) {
    __shared__ float red[8];
    __shared__ float pbuf[256][9];   // padded: conflict-free
    __shared__ float lg[N_EXP];
    int n = blockIdx.x, t = threadIdx.x;
    float* row = g_h + (size_t)n * DM;
    float v[4];
    #pragma unroll
    for (int i = 0; i < 4; ++i) v[i] = row[t + (i << 8)];
    float s = v[0] + v[1] + v[2] + v[3];
    float mean = block_sum256(s, red) * (1.0f / DM);
    float q = 0.f;
    #pragma unroll
    for (int i = 0; i < 4; ++i) { float d = v[i] - mean; q += d * d; }
    float var  = block_sum256(q, red) * (1.0f / DM);
    float rstd = rsqrtf(var + 1e-5f);
    float pl[N_EXP] = {};
    #pragma unroll
    for (int i = 0; i < 4; ++i) {
        int d = t + (i << 8);
        float hn = (v[i] - mean) * rstd * gw[d] + gb[d];
        row[d] = hn;
        const float* wr = wg + (size_t)d * N_EXP;
        #pragma unroll
        for (int e = 0; e < N_EXP; ++e) pl[e] += hn * wr[e];
    }
    #pragma unroll
    for (int e = 0; e < N_EXP; ++e) pbuf[t][e] = pl[e];
    __syncthreads();
    int w = t >> 5, l = t & 31;     // warp w reduces expert w (deterministic)
    float ls = 0.f;
    #pragma unroll
    for (int j = 0; j < 8; ++j) ls += pbuf[l + (j << 5)][w];
    #pragma unroll
    for (int o = 16; o; o >>= 1) ls += __shfl_xor_sync(0xffffffffu, ls, o);
    if (l == 0) lg[w] = ls;
    __syncthreads();
    if (t == 0) {
        float m = lg[0];
        #pragma unroll
        for (int e = 1; e < N_EXP; ++e) m = fmaxf(m, lg[e]);
        float ex[N_EXP], Z = 0.f;
        #pragma unroll
        for (int e = 0; e < N_EXP; ++e) { ex[e] = expf(lg[e] - m); Z += ex[e]; }
        int i0 = 0; float p0 = ex[0];
        #pragma unroll
        for (int e = 1; e < N_EXP; ++e) if (ex[e] > p0) { p0 = ex[e]; i0 = e; }
        int i1 = -1; float p1 = -1.f;
        #pragma unroll
        for (int e = 0; e < N_EXP; ++e)
            if (e != i0 && ex[e] > p1) { p1 = ex[e]; i1 = e; }
        float pa = p0 / Z, pb = p1 / Z;
        float ss = pa + pb + 1e-9f;
        g_top_idx [n * 2 + 0] = i0; g_top_idx [n * 2 + 1] = i1;
        g_top_gate[n * 2 + 0] = pa / ss;
        g_top_gate[n * 2 + 1] = pb / ss;
        atomicAdd(&g_cnt[i0], 1);
        atomicAdd(&g_cnt[i1], 1);
    }
}

__global__ void k_offsets() {
    if (threadIdx.x == 0) {
        int a = 0;
        #pragma unroll
        for (int e = 0; e < N_EXP; ++e) { g_off[e] = a; a += g_cnt[e]; }
    }
}

__global__ void k_scatter() {
    int n = blockIdx.x * blockDim.x + threadIdx.x;
    if (n >= N_TOK) return;
    #pragma unroll
    for (int s = 0; s < TOPK; ++s) {
        int e   = g_top_idx[n * 2 + s];
        int pos = atomicAdd(&g_cursor[e], 1);
        int f   = g_off[e] + pos;
        g_src_tok[f]   = n;
        g_gate_flat[f] = g_top_gate[n * 2 + s];
        g_dst[f]       = n * 2 + s;
    }
}

// act = gelu(gather(h) @ w1[e] + b1[e])   (ragged M per expert, N=2048, K=1024)
__global__ void __launch_bounds__(256)
k_gemm1(const float* __restrict__ W1,
        const float* __restrict__ B1) {
    __shared__ __align__(16) float As[BK][BM];
    __shared__ __align__(16) float Bs[BK][BN];
    __shared__ int toks[BM];
    __shared__ float bsh[BN];
    int bm = blockIdx.x, bn = blockIdx.y;
    int e = 0, accT = 0, cnt = 0;
    for (; e < N_EXP; ++e) {
        cnt = g_cnt[e];
        int tiles = (cnt + BM - 1) / BM;
        if (bm < accT + tiles) break;
        accT += tiles;
    }
    if (e >= N_EXP) return;
    int off = g_off[e];
    int m0  = (bm - accT) * BM;
    int t   = threadIdx.x;
    if (t < BM) {
        int ml = m0 + t;
        toks[t] = (ml < cnt) ? g_src_tok[off + ml] : -1;
        bsh[t] = B1[e * HD + bn * BN + t];
    }
    __syncthreads();
    const float* B = W1 + (size_t)e * DM * HD;
    int la_m = t >> 2,  la_k = (t & 3)  << 2;
    int lb_k = t >> 4,  lb_n = (t & 15) << 2;
    int tx   = (t & 15) << 2, ty = (t >> 4) << 2;
    int tokA = toks[la_m];
    const float* arow = g_h + (size_t)(tokA >= 0 ? tokA : 0) * DM;
    float acc[4][4] = {};
    for (int k0 = 0; k0 < DM; k0 += BK) {
        float4 av = make_float4(0.f, 0.f, 0.f, 0.f);
        if (tokA >= 0) av = *(const float4*)(arow + k0 + la_k);
        As[la_k+0][la_m] = av.x; As[la_k+1][la_m] = av.y;
        As[la_k+2][la_m] = av.z; As[la_k+3][la_m] = av.w;
        *(float4*)&Bs[lb_k][lb_n] =
            *(const float4*)(B + (size_t)(k0 + lb_k) * HD + bn * BN + lb_n);
        __syncthreads();
        GEMM_INNER
        __syncthreads();
    }
    int n0 = bn * BN;
    float4 bv = *(const float4*)&bsh[tx];
    #pragma unroll
    for (int i = 0; i < 4; ++i) {
        int ml = m0 + ty + i;
        if (ml < cnt) {
            float4 o;
            o.x = gelu_tanh(acc[i][0] + bv.x);
            o.y = gelu_tanh(acc[i][1] + bv.y);
            o.z = gelu_tanh(acc[i][2] + bv.z);
            o.w = gelu_tanh(acc[i][3] + bv.w);
            *(float4*)(g_act + (size_t)(off + ml) * HD + n0 + tx) = o;
        }
    }
}

// pair_out = gate * (act @ w2[e] + b2[e])  scattered to (token,slot) rows
__global__ void __launch_bounds__(256)
k_gemm2(const float* __restrict__ W2,
        const float* __restrict__ B2) {
    __shared__ __align__(16) float As[BK][BM];
    __shared__ __align__(16) float Bs[BK][BN];
    __shared__ float gates[BM];
    __shared__ int   dsts[BM];
    __shared__ float bsh[BN];
    int bm = blockIdx.x, bn = blockIdx.y;
    int e = 0, accT = 0, cnt = 0;
    for (; e < N_EXP; ++e) {
        cnt = g_cnt[e];
        int tiles = (cnt + BM - 1) / BM;
        if (bm < accT + tiles) break;
        accT += tiles;
    }
    if (e >= N_EXP) return;
    int off = g_off[e];
    int m0  = (bm - accT) * BM;
    int t   = threadIdx.x;
    if (t < BM) {
        int ml = m0 + t;
        if (ml < cnt) { gates[t] = g_gate_flat[off + ml]; dsts[t] = g_dst[off + ml]; }
        else          { gates[t] = 0.f;                   dsts[t] = -1; }
        bsh[t] = B2[e * DM + bn * BN + t];
    }
    __syncthreads();
    const float* B = W2 + (size_t)e * HD * DM;
    int la_m = t >> 2,  la_k = (t & 3)  << 2;
    int lb_k = t >> 4,  lb_n = (t & 15) << 2;
    int tx   = (t & 15) << 2, ty = (t >> 4) << 2;
    bool avalid = (m0 + la_m) < cnt;
    const float* arow = g_act + (size_t)(off + (avalid ? m0 + la_m : 0)) * HD;
    float acc[4][4] = {};
    for (int k0 = 0; k0 < HD; k0 += BK) {
        float4 av = make_float4(0.f, 0.f, 0.f, 0.f);
        if (avalid) av = *(const float4*)(arow + k0 + la_k);
        As[la_k+0][la_m] = av.x; As[la_k+1][la_m] = av.y;
        As[la_k+2][la_m] = av.z; As[la_k+3][la_m] = av.w;
        *(float4*)&Bs[lb_k][lb_n] =
            *(const float4*)(B + (size_t)(k0 + lb_k) * DM + bn * BN + lb_n);
        __syncthreads();
        GEMM_INNER
        __syncthreads();
    }
    int n0 = bn * BN;
    float4 bv = *(const float4*)&bsh[tx];
    #pragma unroll
    for (int i = 0; i < 4; ++i) {
        int d = dsts[ty + i];
        if (d >= 0) {
            float g = gates[ty + i];
            float4 o;
            o.x = g * (acc[i][0] + bv.x);
            o.y = g * (acc[i][1] + bv.y);
            o.z = g * (acc[i][2] + bv.z);
            o.w = g * (acc[i][3] + bv.w);
            *(float4*)(g_pair + (size_t)d * DM + n0 + tx) = o;
        }
    }
}

// combine + LN(g_moe) + LN(g_out) + classifier
__global__ void __launch_bounds__(256)
k_final(const float* __restrict__ gm, const float* __restrict__ bm_,
        const float* __restrict__ go, const float* __restrict__ bo,
        const float* __restrict__ wc, const float* __restrict__ bc,
        float* __restrict__ out) {
    __shared__ float red[8];
    int n = blockIdx.x, t = threadIdx.x;
    const float* hrow = g_h    + (size_t)n * DM;
    const float* p0   = g_pair + (size_t)(n * 2 + 0) * DM;
    const float* p1   = g_pair + (size_t)(n * 2 + 1) * DM;
    float c[4];
    #pragma unroll
    for (int i = 0; i < 4; ++i) {
        int d = t + (i << 8);
        c[i] = hrow[d] + p0[d] + p1[d];
    }
    float s = c[0] + c[1] + c[2] + c[3];
    float mean = block_sum256(s, red) * (1.0f / DM);
    float q = 0.f;
    #pragma unroll
    for (int i = 0; i < 4; ++i) { float d = c[i] - mean; q += d * d; }
    float rstd = rsqrtf(block_sum256(q, red) * (1.0f / DM) + 1e-5f);
    float y[4];
    #pragma unroll
    for (int i = 0; i < 4; ++i) {
        int d = t + (i << 8);
        y[i] = (c[i] - mean) * rstd * gm[d] + bm_[d];
    }
    // second LN
    float s2 = y[0] + y[1] + y[2] + y[3];
    float mean2 = block_sum256(s2, red) * (1.0f / DM);
    float q2 = 0.f;
    #pragma unroll
    for (int i = 0; i < 4; ++i) { float d = y[i] - mean2; q2 += d * d; }
    float rstd2 = rsqrtf(block_sum256(q2, red) * (1.0f / DM) + 1e-5f);
    float a0 = 0.f, a1 = 0.f;
    #pragma unroll
    for (int i = 0; i < 4; ++i) {
        int d = t + (i << 8);
        float z = (y[i] - mean2) * rstd2 * go[d] + bo[d];
        a0 += z * wc[d * 2 + 0];
        a1 += z * wc[d * 2 + 1];
    }
    a0 = block_sum256(a0, red);
    a1 = block_sum256(a1, red);
    if (t == 0) {
        out[n * 2 + 0] = a0 + bc[0];
        out[n * 2 + 1] = a1 + bc[1];
    }
}

// ---------------- launch ----------------
extern "C" void kernel_launch(void* const* d_in, const int* in_sizes, int n_in,
                              void* d_out, int out_size) {
    const float* x     = (const float*)d_in[0];
    const float* w_in  = (const float*)d_in[1];
    const float* b_in  = (const float*)d_in[2];
    const float* g_in  = (const float*)d_in[3];
    const float* be_in = (const float*)d_in[4];
    const float* w_g   = (const float*)d_in[5];
    const float* w1    = (const float*)d_in[6];
    const float* b1    = (const float*)d_in[7];
    const float* w2    = (const float*)d_in[8];
    const float* b2    = (const float*)d_in[9];
    const float* g_mo  = (const float*)d_in[10];
    const float* be_mo = (const float*)d_in[11];
    const float* g_ou  = (const float*)d_in[12];
    const float* be_ou = (const float*)d_in[13];
    const float* w_c   = (const float*)d_in[14];
    const float* b_c   = (const float*)d_in[15];
    float* out = (float*)d_out;

    k_zero<<<1, 32>>>();
    k_gemm_in<<<dim3(N_TOK / BM, DM / BN), 256>>>(x, w_in, b_in);
    k_ln_router<<<N_TOK, 256>>>(g_in, be_in, w_g);
    k_offsets<<<1, 32>>>();
    k_scatter<<<N_TOK / 256, 256>>>();
    k_gemm1<<<dim3(MAXMT, HD / BN), 256>>>(w1, b1);
    k_gemm2<<<dim3(MAXMT, DM / BN), 256>>>(w2, b2);
    k_final<<<N_TOK, 256>>>(g_mo, be_mo, g_ou, be_ou, w_c, b_c, out);
}

// round 6
// speedup vs baseline: 1.0101x; 1.0101x over previous
#include <cuda_runtime.h>
#include <math.h>

// ---------------- problem constants ----------------
#define N_TOK   16384
#define DIN     256
#define DM      1024
#define HD      2048
#define N_EXP   8
#define TOPK    2
#define N_OUT   2
#define NKPAIR  (N_TOK * TOPK)          // 32768 token-expert pairs

// ---------------- GEMM tiling ----------------
#define BM 64
#define BN 64
#define BK 16
#define MAXMT ((NKPAIR / BM) + N_EXP)   // 520: worst-case ragged M tiles

// ---------------- scratch (device globals; no allocation allowed) ----------
__device__ __align__(16) float g_h[(size_t)N_TOK * DM];       // 64 MB: normalized h
__device__ __align__(16) float g_act[(size_t)NKPAIR * HD];    // 256 MB: gelu activations
__device__ __align__(16) float g_pair[(size_t)NKPAIR * DM];   // 128 MB: gated expert outputs
__device__ int   g_cnt[N_EXP];
__device__ int   g_cursor[N_EXP];
__device__ int   g_off[N_EXP];
__device__ int   g_top_idx[N_TOK * TOPK];
__device__ float g_top_gate[N_TOK * TOPK];
__device__ int   g_src_tok[NKPAIR];
__device__ float g_gate_flat[NKPAIR];
__device__ int   g_dst[NKPAIR];

// ---------------- packed f32x2 helpers (Blackwell FFMA2 path) -------------
typedef unsigned long long u64t;

__device__ __forceinline__ u64t pk2(float x, float y) {
    u64t r;
    asm("mov.b64 %0, {%1, %2};" : "=l"(r) : "f"(x), "f"(y));
    return r;
}
__device__ __forceinline__ void ffma2(u64t& d, u64t a, u64t b) {
    // d = a * b + d, two independent fp32 lanes per instruction
    asm("fma.rn.f32x2 %0, %1, %2, %0;" : "+l"(d) : "l"(a), "l"(b));
}
__device__ __forceinline__ float2 upk2(u64t v) {
    float2 f;
    asm("mov.b64 {%0, %1}, %2;" : "=f"(f.x), "=f"(f.y) : "l"(v));
    return f;
}

// acc2[i][0] = cols(tx+0,tx+1) of row i; acc2[i][1] = cols(tx+2,tx+3)
#define GEMM_INNER2                                                             \
    _Pragma("unroll")                                                           \
    for (int kk = 0; kk < BK; ++kk) {                                           \
        float4 a = *(const float4*)&As[kk][ty];                                 \
        float4 b = *(const float4*)&Bs[kk][tx];                                 \
        u64t b01 = pk2(b.x, b.y), b23 = pk2(b.z, b.w);                          \
        u64t a0 = pk2(a.x, a.x), a1 = pk2(a.y, a.y);                            \
        u64t a2 = pk2(a.z, a.z), a3 = pk2(a.w, a.w);                            \
        ffma2(acc2[0][0], a0, b01); ffma2(acc2[0][1], a0, b23);                 \
        ffma2(acc2[1][0], a1, b01); ffma2(acc2[1][1], a1, b23);                 \
        ffma2(acc2[2][0], a2, b01); ffma2(acc2[2][1], a2, b23);                 \
        ffma2(acc2[3][0], a3, b01); ffma2(acc2[3][1], a3, b23);                 \
    }

// ---------------- helpers ----------------
__device__ __forceinline__ float block_sum256(float v, float* red) {
    #pragma unroll
    for (int o = 16; o; o >>= 1) v += __shfl_xor_sync(0xffffffffu, v, o);
    __syncthreads();                       // protect red from prior use
    if ((threadIdx.x & 31) == 0) red[threadIdx.x >> 5] = v;
    __syncthreads();
    float s = 0.f;
    #pragma unroll
    for (int i = 0; i < 8; ++i) s += red[i];
    return s;
}

__device__ __forceinline__ float gelu_tanh(float x) {
    // jax.nn.gelu default (approximate=True)
    float x3 = x * x * x;
    float u  = 0.7978845608028654f * (x + 0.044715f * x3);
    return 0.5f * x * (1.0f + tanhf(u));
}

// ---------------- kernels ----------------
__global__ void k_zero() {
    int t = threadIdx.x;
    if (t < N_EXP) { g_cnt[t] = 0; g_cursor[t] = 0; }
}

// h_pre = x @ w_in + b_in   (M=16384, N=1024, K=256), fp32
__global__ void __launch_bounds__(256)
k_gemm_in(const float* __restrict__ X,
          const float* __restrict__ W,
          const float* __restrict__ bias) {
    __shared__ __align__(16) float As[BK][BM];
    __shared__ __align__(16) float Bs[BK][BN];
    __shared__ float bsh[BN];
    int t = threadIdx.x;
    int m0 = blockIdx.x * BM, n0 = blockIdx.y * BN;
    if (t < BN) bsh[t] = bias[n0 + t];
    int la_m = t >> 2,  la_k = (t & 3)  << 2;
    int lb_k = t >> 4,  lb_n = (t & 15) << 2;
    int tx   = (t & 15) << 2, ty = (t >> 4) << 2;
    u64t acc2[4][2] = {};
    for (int k0 = 0; k0 < DIN; k0 += BK) {
        float4 av = *(const float4*)(X + (size_t)(m0 + la_m) * DIN + k0 + la_k);
        As[la_k+0][la_m] = av.x; As[la_k+1][la_m] = av.y;
        As[la_k+2][la_m] = av.z; As[la_k+3][la_m] = av.w;
        *(float4*)&Bs[lb_k][lb_n] =
            *(const float4*)(W + (size_t)(k0 + lb_k) * DM + n0 + lb_n);
        __syncthreads();
        GEMM_INNER2
        __syncthreads();
    }
    float4 bv = *(const float4*)&bsh[tx];
    #pragma unroll
    for (int i = 0; i < 4; ++i) {
        float2 c01 = upk2(acc2[i][0]), c23 = upk2(acc2[i][1]);
        float4 o;
        o.x = c01.x + bv.x;
        o.y = c01.y + bv.y;
        o.z = c23.x + bv.z;
        o.w = c23.y + bv.w;
        *(float4*)(g_h + (size_t)(m0 + ty + i) * DM + n0 + tx) = o;
    }
}

// per-token: LN(h_pre) in place; router logits, softmax, top-2, gates, counts
__global__ void __launch_bounds__(256)
k_ln_router(const float* __restrict__ gw,
            const float* __restrict__ gb,
            const float* __restrict__ wg) {
    __shared__ float red[8];
    __shared__ float pbuf[256][9];   // padded: conflict-free
    __shared__ float lg[N_EXP];
    int n = blockIdx.x, t = threadIdx.x;
    float* row = g_h + (size_t)n * DM;
    float v[4];
    #pragma unroll
    for (int i = 0; i < 4; ++i) v[i] = row[t + (i << 8)];
    float s = v[0] + v[1] + v[2] + v[3];
    float mean = block_sum256(s, red) * (1.0f / DM);
    float q = 0.f;
    #pragma unroll
    for (int i = 0; i < 4; ++i) { float d = v[i] - mean; q += d * d; }
    float var  = block_sum256(q, red) * (1.0f / DM);
    float rstd = rsqrtf(var + 1e-5f);
    float pl[N_EXP] = {};
    #pragma unroll
    for (int i = 0; i < 4; ++i) {
        int d = t + (i << 8);
        float hn = (v[i] - mean) * rstd * gw[d] + gb[d];
        row[d] = hn;
        const float* wr = wg + (size_t)d * N_EXP;
        #pragma unroll
        for (int e = 0; e < N_EXP; ++e) pl[e] += hn * wr[e];
    }
    #pragma unroll
    for (int e = 0; e < N_EXP; ++e) pbuf[t][e] = pl[e];
    __syncthreads();
    int w = t >> 5, l = t & 31;     // warp w reduces expert w (deterministic)
    float ls = 0.f;
    #pragma unroll
    for (int j = 0; j < 8; ++j) ls += pbuf[l + (j << 5)][w];
    #pragma unroll
    for (int o = 16; o; o >>= 1) ls += __shfl_xor_sync(0xffffffffu, ls, o);
    if (l == 0) lg[w] = ls;
    __syncthreads();
    if (t == 0) {
        float m = lg[0];
        #pragma unroll
        for (int e = 1; e < N_EXP; ++e) m = fmaxf(m, lg[e]);
        float ex[N_EXP], Z = 0.f;
        #pragma unroll
        for (int e = 0; e < N_EXP; ++e) { ex[e] = expf(lg[e] - m); Z += ex[e]; }
        int i0 = 0; float p0 = ex[0];
        #pragma unroll
        for (int e = 1; e < N_EXP; ++e) if (ex[e] > p0) { p0 = ex[e]; i0 = e; }
        int i1 = -1; float p1 = -1.f;
        #pragma unroll
        for (int e = 0; e < N_EXP; ++e)
            if (e != i0 && ex[e] > p1) { p1 = ex[e]; i1 = e; }
        float pa = p0 / Z, pb = p1 / Z;
        float ss = pa + pb + 1e-9f;
        g_top_idx [n * 2 + 0] = i0; g_top_idx [n * 2 + 1] = i1;
        g_top_gate[n * 2 + 0] = pa / ss;
        g_top_gate[n * 2 + 1] = pb / ss;
        atomicAdd(&g_cnt[i0], 1);
        atomicAdd(&g_cnt[i1], 1);
    }
}

__global__ void k_offsets() {
    if (threadIdx.x == 0) {
        int a = 0;
        #pragma unroll
        for (int e = 0; e < N_EXP; ++e) { g_off[e] = a; a += g_cnt[e]; }
    }
}

__global__ void k_scatter() {
    int n = blockIdx.x * blockDim.x + threadIdx.x;
    if (n >= N_TOK) return;
    #pragma unroll
    for (int s = 0; s < TOPK; ++s) {
        int e   = g_top_idx[n * 2 + s];
        int pos = atomicAdd(&g_cursor[e], 1);
        int f   = g_off[e] + pos;
        g_src_tok[f]   = n;
        g_gate_flat[f] = g_top_gate[n * 2 + s];
        g_dst[f]       = n * 2 + s;
    }
}

// act = gelu(gather(h) @ w1[e] + b1[e])   (ragged M per expert, N=2048, K=1024)
__global__ void __launch_bounds__(256)
k_gemm1(const float* __restrict__ W1,
        const float* __restrict__ B1) {
    __shared__ __align__(16) float As[BK][BM];
    __shared__ __align__(16) float Bs[BK][BN];
    __shared__ int toks[BM];
    __shared__ float bsh[BN];
    int bm = blockIdx.x, bn = blockIdx.y;
    int e = 0, accT = 0, cnt = 0;
    for (; e < N_EXP; ++e) {
        cnt = g_cnt[e];
        int tiles = (cnt + BM - 1) / BM;
        if (bm < accT + tiles) break;
        accT += tiles;
    }
    if (e >= N_EXP) return;
    int off = g_off[e];
    int m0  = (bm - accT) * BM;
    int t   = threadIdx.x;
    if (t < BM) {
        int ml = m0 + t;
        toks[t] = (ml < cnt) ? g_src_tok[off + ml] : -1;
        bsh[t] = B1[e * HD + bn * BN + t];
    }
    __syncthreads();
    const float* B = W1 + (size_t)e * DM * HD;
    int la_m = t >> 2,  la_k = (t & 3)  << 2;
    int lb_k = t >> 4,  lb_n = (t & 15) << 2;
    int tx   = (t & 15) << 2, ty = (t >> 4) << 2;
    int tokA = toks[la_m];
    const float* arow = g_h + (size_t)(tokA >= 0 ? tokA : 0) * DM;
    u64t acc2[4][2] = {};
    for (int k0 = 0; k0 < DM; k0 += BK) {
        float4 av = make_float4(0.f, 0.f, 0.f, 0.f);
        if (tokA >= 0) av = *(const float4*)(arow + k0 + la_k);
        As[la_k+0][la_m] = av.x; As[la_k+1][la_m] = av.y;
        As[la_k+2][la_m] = av.z; As[la_k+3][la_m] = av.w;
        *(float4*)&Bs[lb_k][lb_n] =
            *(const float4*)(B + (size_t)(k0 + lb_k) * HD + bn * BN + lb_n);
        __syncthreads();
        GEMM_INNER2
        __syncthreads();
    }
    int n0 = bn * BN;
    float4 bv = *(const float4*)&bsh[tx];
    #pragma unroll
    for (int i = 0; i < 4; ++i) {
        int ml = m0 + ty + i;
        if (ml < cnt) {
            float2 c01 = upk2(acc2[i][0]), c23 = upk2(acc2[i][1]);
            float4 o;
            o.x = gelu_tanh(c01.x + bv.x);
            o.y = gelu_tanh(c01.y + bv.y);
            o.z = gelu_tanh(c23.x + bv.z);
            o.w = gelu_tanh(c23.y + bv.w);
            *(float4*)(g_act + (size_t)(off + ml) * HD + n0 + tx) = o;
        }
    }
}

// pair_out = gate * (act @ w2[e] + b2[e])  scattered to (token,slot) rows
__global__ void __launch_bounds__(256)
k_gemm2(const float* __restrict__ W2,
        const float* __restrict__ B2) {
    __shared__ __align__(16) float As[BK][BM];
    __shared__ __align__(16) float Bs[BK][BN];
    __shared__ float gates[BM];
    __shared__ int   dsts[BM];
    __shared__ float bsh[BN];
    int bm = blockIdx.x, bn = blockIdx.y;
    int e = 0, accT = 0, cnt = 0;
    for (; e < N_EXP; ++e) {
        cnt = g_cnt[e];
        int tiles = (cnt + BM - 1) / BM;
        if (bm < accT + tiles) break;
        accT += tiles;
    }
    if (e >= N_EXP) return;
    int off = g_off[e];
    int m0  = (bm - accT) * BM;
    int t   = threadIdx.x;
    if (t < BM) {
        int ml = m0 + t;
        if (ml < cnt) { gates[t] = g_gate_flat[off + ml]; dsts[t] = g_dst[off + ml]; }
        else          { gates[t] = 0.f;                   dsts[t] = -1; }
        bsh[t] = B2[e * DM + bn * BN + t];
    }
    __syncthreads();
    const float* B = W2 + (size_t)e * HD * DM;
    int la_m = t >> 2,  la_k = (t & 3)  << 2;
    int lb_k = t >> 4,  lb_n = (t & 15) << 2;
    int tx   = (t & 15) << 2, ty = (t >> 4) << 2;
    bool avalid = (m0 + la_m) < cnt;
    const float* arow = g_act + (size_t)(off + (avalid ? m0 + la_m : 0)) * HD;
    u64t acc2[4][2] = {};
    for (int k0 = 0; k0 < HD; k0 += BK) {
        float4 av = make_float4(0.f, 0.f, 0.f, 0.f);
        if (avalid) av = *(const float4*)(arow + k0 + la_k);
        As[la_k+0][la_m] = av.x; As[la_k+1][la_m] = av.y;
        As[la_k+2][la_m] = av.z; As[la_k+3][la_m] = av.w;
        *(float4*)&Bs[lb_k][lb_n] =
            *(const float4*)(B + (size_t)(k0 + lb_k) * DM + bn * BN + lb_n);
        __syncthreads();
        GEMM_INNER2
        __syncthreads();
    }
    int n0 = bn * BN;
    float4 bv = *(const float4*)&bsh[tx];
    #pragma unroll
    for (int i = 0; i < 4; ++i) {
        int d = dsts[ty + i];
        if (d >= 0) {
            float g = gates[ty + i];
            float2 c01 = upk2(acc2[i][0]), c23 = upk2(acc2[i][1]);
            float4 o;
            o.x = g * (c01.x + bv.x);
            o.y = g * (c01.y + bv.y);
            o.z = g * (c23.x + bv.z);
            o.w = g * (c23.y + bv.w);
            *(float4*)(g_pair + (size_t)d * DM + n0 + tx) = o;
        }
    }
}

// combine + LN(g_moe) + LN(g_out) + classifier
__global__ void __launch_bounds__(256)
k_final(const float* __restrict__ gm, const float* __restrict__ bm_,
        const float* __restrict__ go, const float* __restrict__ bo,
        const float* __restrict__ wc, const float* __restrict__ bc,
        float* __restrict__ out) {
    __shared__ float red[8];
    int n = blockIdx.x, t = threadIdx.x;
    const float* hrow = g_h    + (size_t)n * DM;
    const float* p0   = g_pair + (size_t)(n * 2 + 0) * DM;
    const float* p1   = g_pair + (size_t)(n * 2 + 1) * DM;
    float c[4];
    #pragma unroll
    for (int i = 0; i < 4; ++i) {
        int d = t + (i << 8);
        c[i] = hrow[d] + p0[d] + p1[d];
    }
    float s = c[0] + c[1] + c[2] + c[3];
    float mean = block_sum256(s, red) * (1.0f / DM);
    float q = 0.f;
    #pragma unroll
    for (int i = 0; i < 4; ++i) { float d = c[i] - mean; q += d * d; }
    float rstd = rsqrtf(block_sum256(q, red) * (1.0f / DM) + 1e-5f);
    float y[4];
    #pragma unroll
    for (int i = 0; i < 4; ++i) {
        int d = t + (i << 8);
        y[i] = (c[i] - mean) * rstd * gm[d] + bm_[d];
    }
    // second LN
    float s2 = y[0] + y[1] + y[2] + y[3];
    float mean2 = block_sum256(s2, red) * (1.0f / DM);
    float q2 = 0.f;
    #pragma unroll
    for (int i = 0; i < 4; ++i) { float d = y[i] - mean2; q2 += d * d; }
    float rstd2 = rsqrtf(block_sum256(q2, red) * (1.0f / DM) + 1e-5f);
    float a0 = 0.f, a1 = 0.f;
    #pragma unroll
    for (int i = 0; i < 4; ++i) {
        int d = t + (i << 8);
        float z = (y[i] - mean2) * rstd2 * go[d] + bo[d];
        a0 += z * wc[d * 2 + 0];
        a1 += z * wc[d * 2 + 1];
    }
    a0 = block_sum256(a0, red);
    a1 = block_sum256(a1, red);
    if (t == 0) {
        out[n * 2 + 0] = a0 + bc[0];
        out[n * 2 + 1] = a1 + bc[1];
    }
}

// ---------------- launch ----------------
extern "C" void kernel_launch(void* const* d_in, const int* in_sizes, int n_in,
                              void* d_out, int out_size) {
    const float* x     = (const float*)d_in[0];
    const float* w_in  = (const float*)d_in[1];
    const float* b_in  = (const float*)d_in[2];
    const float* g_in  = (const float*)d_in[3];
    const float* be_in = (const float*)d_in[4];
    const float* w_g   = (const float*)d_in[5];
    const float* w1    = (const float*)d_in[6];
    const float* b1    = (const float*)d_in[7];
    const float* w2    = (const float*)d_in[8];
    const float* b2    = (const float*)d_in[9];
    const float* g_mo  = (const float*)d_in[10];
    const float* be_mo = (const float*)d_in[11];
    const float* g_ou  = (const float*)d_in[12];
    const float* be_ou = (const float*)d_in[13];
    const float* w_c   = (const float*)d_in[14];
    const float* b_c   = (const float*)d_in[15];
    float* out = (float*)d_out;

    k_zero<<<1, 32>>>();
    k_gemm_in<<<dim3(N_TOK / BM, DM / BN), 256>>>(x, w_in, b_in);
    k_ln_router<<<N_TOK, 256>>>(g_in, be_in, w_g);
    k_offsets<<<1, 32>>>();
    k_scatter<<<N_TOK / 256, 256>>>();
    k_gemm1<<<dim3(MAXMT, HD / BN), 256>>>(w1, b1);
    k_gemm2<<<dim3(MAXMT, DM / BN), 256>>>(w2, b2);
    k_final<<<N_TOK, 256>>>(g_mo, be_mo, g_ou, be_ou, w_c, b_c, out);
}

// round 16
// speedup vs baseline: 1.4677x; 1.4530x over previous
#include <cuda_runtime.h>
#include <stdint.h>
#include <math.h>

#define N_TOK 16384
#define DIN 256
#define DM 1024
#define HD 2048
#define N_EXP 8
#define NKPAIR 32768

#define BM 64
#define BN 64
#define BK 16

#define MTILE 128
#define NTILE 64
#define KS 16
#define SROW 20            // padded smem row stride in floats
#define MT2 ((NKPAIR / MTILE) + N_EXP)

__device__ __align__(16) float g_h[(size_t)N_TOK * DM];
__device__ __align__(16) float g_act[(size_t)NKPAIR * HD];
__device__ __align__(16) float g_pair[(size_t)NKPAIR * DM];
__device__ int g_cnt[N_EXP];
__device__ int g_cursor[N_EXP];
__device__ int g_off[N_EXP];
__device__ int g_top_idx[N_TOK * 2];
__device__ float g_top_gate[N_TOK * 2];
__device__ int g_src_tok[NKPAIR];
__device__ float g_gate_flat[NKPAIR];
__device__ int g_dst[NKPAIR];

// tf32 m16n8k8 mma, fp32 accum (sm_80 base-target), scalar b32 operands
__device__ __forceinline__ void mma_tf32(float& c0, float& c1, float& c2, float& c3,
                                         uint32_t a0, uint32_t a1, uint32_t a2, uint32_t a3,
                                         uint32_t b0, uint32_t b1) {
    asm volatile("mma.sync.aligned.m16n8k8.row.col.f32.tf32.tf32.f32 "
        "{%0,%1,%2,%3}, {%4,%5,%6,%7}, {%8,%9}, {%0,%1,%2,%3};"
        : "+f"(c0), "+f"(c1), "+f"(c2), "+f"(c3)
        : "r"(a0), "r"(a1), "r"(a2), "r"(a3), "r"(b0), "r"(b1));
}

// exact split: hi = tf32-truncated v (bitmask), lo = v - hi (exact in fp32)
__device__ __forceinline__ uint32_t tf32_hi_bits(float v) {
    return __float_as_uint(v) & 0xFFFFE000u;
}

__device__ __forceinline__ float block_sum256(float v, float* red) {
    #pragma unroll
    for (int o = 16; o > 0; o = o >> 1) {
        v += __shfl_xor_sync(0xffffffffu, v, o);
    }
    __syncthreads();
    if ((threadIdx.x & 31) == 0) red[threadIdx.x >> 5] = v;
    __syncthreads();
    float s = 0.0f;
    #pragma unroll
    for (int i = 0; i < 8; ++i) s += red[i];
    return s;
}

__device__ __forceinline__ float gelu_tanh(float x) {
    float x3 = x * x * x;
    float u = 0.7978845608028654f * (x + 0.044715f * x3);
    return 0.5f * x * (1.0f + tanhf(u));
}

__global__ void k_zero() {
    int t = threadIdx.x;
    if (t < N_EXP) {
        g_cnt[t] = 0;
        g_cursor[t] = 0;
    }
}

__global__ void __launch_bounds__(256)
k_gemm_in(const float* __restrict__ X, const float* __restrict__ W,
          const float* __restrict__ bias) {
    __shared__ __align__(16) float As[BK][BM];
    __shared__ __align__(16) float Bs[BK][BN];
    __shared__ float bsh[BN];
    int t = threadIdx.x;
    int m0 = blockIdx.x * BM;
    int n0 = blockIdx.y * BN;
    if (t < BN) bsh[t] = bias[n0 + t];
    int la_m = t >> 2;
    int la_k = (t & 3) << 2;
    int lb_k = t >> 4;
    int lb_n = (t & 15) << 2;
    int tx = (t & 15) << 2;
    int ty = (t >> 4) << 2;
    float acc[4][4] = {};
    for (int k0 = 0; k0 < DIN; k0 += BK) {
        float4 av = *(const float4*)(X + (size_t)(m0 + la_m) * DIN + k0 + la_k);
        As[la_k + 0][la_m] = av.x;
        As[la_k + 1][la_m] = av.y;
        As[la_k + 2][la_m] = av.z;
        As[la_k + 3][la_m] = av.w;
        *(float4*)(&Bs[lb_k][lb_n]) = *(const float4*)(W + (size_t)(k0 + lb_k) * DM + n0 + lb_n);
        __syncthreads();
        #pragma unroll
        for (int kk = 0; kk < BK; ++kk) {
            float4 a = *(const float4*)(&As[kk][ty]);
            float4 b = *(const float4*)(&Bs[kk][tx]);
            acc[0][0] += a.x * b.x; acc[0][1] += a.x * b.y; acc[0][2] += a.x * b.z; acc[0][3] += a.x * b.w;
            acc[1][0] += a.y * b.x; acc[1][1] += a.y * b.y; acc[1][2] += a.y * b.z; acc[1][3] += a.y * b.w;
            acc[2][0] += a.z * b.x; acc[2][1] += a.z * b.y; acc[2][2] += a.z * b.z; acc[2][3] += a.z * b.w;
            acc[3][0] += a.w * b.x; acc[3][1] += a.w * b.y; acc[3][2] += a.w * b.z; acc[3][3] += a.w * b.w;
        }
        __syncthreads();
    }
    float4 bv = *(const float4*)(&bsh[tx]);
    #pragma unroll
    for (int i = 0; i < 4; ++i) {
        float4 o;
        o.x = acc[i][0] + bv.x;
        o.y = acc[i][1] + bv.y;
        o.z = acc[i][2] + bv.z;
        o.w = acc[i][3] + bv.w;
        *(float4*)(g_h + (size_t)(m0 + ty + i) * DM + n0 + tx) = o;
    }
}

__global__ void __launch_bounds__(256)
k_ln_router(const float* __restrict__ gw, const float* __restrict__ gb,
            const float* __restrict__ wg) {
    __shared__ float red[8];
    __shared__ float pbuf[256][9];
    __shared__ float lg[N_EXP];
    int n = blockIdx.x;
    int t = threadIdx.x;
    float* row = g_h + (size_t)n * DM;
    float v[4];
    #pragma unroll
    for (int i = 0; i < 4; ++i) v[i] = row[t + i * 256];
    float s = v[0] + v[1] + v[2] + v[3];
    float mean = block_sum256(s, red) * (1.0f / DM);
    float q = 0.0f;
    #pragma unroll
    for (int i = 0; i < 4; ++i) {
        float d = v[i] - mean;
        q += d * d;
    }
    float var = block_sum256(q, red) * (1.0f / DM);
    float rstd = rsqrtf(var + 1e-5f);
    float pl[N_EXP] = {};
    #pragma unroll
    for (int i = 0; i < 4; ++i) {
        int d = t + i * 256;
        float hn = (v[i] - mean) * rstd * gw[d] + gb[d];
        row[d] = hn;
        const float* wr = wg + (size_t)d * N_EXP;
        #pragma unroll
        for (int e = 0; e < N_EXP; ++e) pl[e] += hn * wr[e];
    }
    #pragma unroll
    for (int e = 0; e < N_EXP; ++e) pbuf[t][e] = pl[e];
    __syncthreads();
    int w = t >> 5;
    int l = t & 31;
    float ls = 0.0f;
    #pragma unroll
    for (int j = 0; j < 8; ++j) ls += pbuf[l + j * 32][w];
    #pragma unroll
    for (int o = 16; o > 0; o = o >> 1) {
        ls += __shfl_xor_sync(0xffffffffu, ls, o);
    }
    if (l == 0) lg[w] = ls;
    __syncthreads();
    if (t == 0) {
        float m = lg[0];
        #pragma unroll
        for (int e = 1; e < N_EXP; ++e) m = fmaxf(m, lg[e]);
        float ex[N_EXP];
        float Z = 0.0f;
        #pragma unroll
        for (int e = 0; e < N_EXP; ++e) {
            ex[e] = expf(lg[e] - m);
            Z += ex[e];
        }
        int i0 = 0;
        float p0 = ex[0];
        #pragma unroll
        for (int e = 1; e < N_EXP; ++e) {
            if (ex[e] > p0) {
                p0 = ex[e];
                i0 = e;
            }
        }
        int i1 = -1;
        float p1 = -1.0f;
        #pragma unroll
        for (int e = 0; e < N_EXP; ++e) {
            if (e != i0 && ex[e] > p1) {
                p1 = ex[e];
                i1 = e;
            }
        }
        float pa = p0 / Z;
        float pb = p1 / Z;
        float ss = pa + pb + 1e-9f;
        g_top_idx[n * 2 + 0] = i0;
        g_top_idx[n * 2 + 1] = i1;
        g_top_gate[n * 2 + 0] = pa / ss;
        g_top_gate[n * 2 + 1] = pb / ss;
        atomicAdd(&g_cnt[i0], 1);
        atomicAdd(&g_cnt[i1], 1);
    }
}

__global__ void k_offsets() {
    if (threadIdx.x == 0) {
        int a = 0;
        #pragma unroll
        for (int e = 0; e < N_EXP; ++e) {
            g_off[e] = a;
            a += g_cnt[e];
        }
    }
}

__global__ void k_scatter() {
    int n = blockIdx.x * blockDim.x + threadIdx.x;
    if (n >= N_TOK) return;
    #pragma unroll
    for (int s = 0; s < 2; ++s) {
        int e = g_top_idx[n * 2 + s];
        int pos = atomicAdd(&g_cursor[e], 1);
        int f = g_off[e] + pos;
        g_src_tok[f] = n;
        g_gate_flat[f] = g_top_gate[n * 2 + s];
        g_dst[f] = n * 2 + s;
    }
}

// expert up: act = gelu(gather(h) @ w1[e] + b1), tf32 3-term split mma
// block tile 128x64, 8 warps (4 row x 2 col), 32x32 per warp
__global__ void __launch_bounds__(256)
k_mma1(const float* __restrict__ W1, const float* __restrict__ B1) {
    __shared__ __align__(16) float sA[MTILE * SROW];
    __shared__ __align__(16) float sB[NTILE * SROW];
    __shared__ int toks[MTILE];
    __shared__ float bsh[NTILE];
    int t = threadIdx.x;
    int bm = blockIdx.x;
    int bn = blockIdx.y;
    int e = 0;
    int acct = 0;
    int cnt = 0;
    for (; e < N_EXP; ++e) {
        cnt = g_cnt[e];
        int tiles = (cnt + MTILE - 1) / MTILE;
        if (bm < acct + tiles) break;
        acct += tiles;
    }
    if (e >= N_EXP) return;
    int off = g_off[e];
    int m0 = (bm - acct) * MTILE;
    if (t < MTILE) {
        int ml = m0 + t;
        toks[t] = (ml < cnt) ? g_src_tok[off + ml] : -1;
    }
    if (t < NTILE) bsh[t] = B1[e * HD + bn * NTILE + t];
    __syncthreads();
    int warp = t >> 5;
    int lane = t & 31;
    int wm = warp >> 1;
    int wn = warp & 1;
    int gid = lane >> 2;
    int tig = lane & 3;
    float acc[2][4][4] = {};
    for (int k0 = 0; k0 < DM; k0 += KS) {
        // A fill: 128 rows x 4 float4-chunks = 512, 2 per thread
        #pragma unroll
        for (int cc = 0; cc < 2; ++cc) {
            int c = t + cc * 256;
            int row = c >> 2;
            int q = c & 3;
            int tok = toks[row];
            float4 v = make_float4(0.f, 0.f, 0.f, 0.f);
            if (tok >= 0) v = *(const float4*)(g_h + (size_t)tok * DM + k0 + q * 4);
            *(float4*)(&sA[row * SROW + q * 4]) = v;
        }
        // B fill (transpose): 16 k-rows x 64 n = 1024, 4 per thread
        {
            int kk = t >> 4;
            int n4 = (t & 15) << 2;
            float4 v = *(const float4*)(W1 + ((size_t)e * DM + k0 + kk) * HD + (size_t)bn * NTILE + n4);
            sB[(n4 + 0) * SROW + kk] = v.x;
            sB[(n4 + 1) * SROW + kk] = v.y;
            sB[(n4 + 2) * SROW + kk] = v.z;
            sB[(n4 + 3) * SROW + kk] = v.w;
        }
        __syncthreads();
        #pragma unroll
        for (int ks = 0; ks < 2; ++ks) {
            int kb = ks * 8;
            uint32_t bhi[4][2];
            uint32_t blo[4][2];
            #pragma unroll
            for (int nt = 0; nt < 4; ++nt) {
                int nr = wn * 32 + nt * 8 + gid;
                float v0 = sB[nr * SROW + kb + tig];
                float v1 = sB[nr * SROW + kb + tig + 4];
                uint32_t h0 = tf32_hi_bits(v0);
                uint32_t h1 = tf32_hi_bits(v1);
                bhi[nt][0] = h0;
                bhi[nt][1] = h1;
                blo[nt][0] = __float_as_uint(v0 - __uint_as_float(h0));
                blo[nt][1] = __float_as_uint(v1 - __uint_as_float(h1));
            }
            #pragma unroll
            for (int mt = 0; mt < 2; ++mt) {
                int r0 = wm * 32 + mt * 16 + gid;
                float a0f = sA[r0 * SROW + kb + tig];
                float a1f = sA[(r0 + 8) * SROW + kb + tig];
                float a2f = sA[r0 * SROW + kb + tig + 4];
                float a3f = sA[(r0 + 8) * SROW + kb + tig + 4];
                uint32_t ah0 = tf32_hi_bits(a0f);
                uint32_t ah1 = tf32_hi_bits(a1f);
                uint32_t ah2 = tf32_hi_bits(a2f);
                uint32_t ah3 = tf32_hi_bits(a3f);
                uint32_t al0 = __float_as_uint(a0f - __uint_as_float(ah0));
                uint32_t al1 = __float_as_uint(a1f - __uint_as_float(ah1));
                uint32_t al2 = __float_as_uint(a2f - __uint_as_float(ah2));
                uint32_t al3 = __float_as_uint(a3f - __uint_as_float(ah3));
                #pragma unroll
                for (int nt = 0; nt < 4; ++nt) {
                    mma_tf32(acc[mt][nt][0], acc[mt][nt][1], acc[mt][nt][2], acc[mt][nt][3],
                             ah0, ah1, ah2, ah3, bhi[nt][0], bhi[nt][1]);
                    mma_tf32(acc[mt][nt][0], acc[mt][nt][1], acc[mt][nt][2], acc[mt][nt][3],
                             ah0, ah1, ah2, ah3, blo[nt][0], blo[nt][1]);
                    mma_tf32(acc[mt][nt][0], acc[mt][nt][1], acc[mt][nt][2], acc[mt][nt][3],
                             al0, al1, al2, al3, bhi[nt][0], bhi[nt][1]);
                }
            }
        }
        __syncthreads();
    }
    #pragma unroll
    for (int mt = 0; mt < 2; ++mt) {
        int rloc0 = wm * 32 + mt * 16 + gid;
        int rloc1 = rloc0 + 8;
        int ml0 = m0 + rloc0;
        int ml1 = m0 + rloc1;
        #pragma unroll
        for (int nt = 0; nt < 4; ++nt) {
            int cl = wn * 32 + nt * 8 + tig * 2;
            int col = bn * NTILE + cl;
            float bx = bsh[cl];
            float by = bsh[cl + 1];
            if (ml0 < cnt) {
                float2 o;
                o.x = gelu_tanh(acc[mt][nt][0] + bx);
                o.y = gelu_tanh(acc[mt][nt][1] + by);
                *(float2*)(g_act + (size_t)(off + ml0) * HD + col) = o;
            }
            if (ml1 < cnt) {
                float2 o;
                o.x = gelu_tanh(acc[mt][nt][2] + bx);
                o.y = gelu_tanh(acc[mt][nt][3] + by);
                *(float2*)(g_act + (size_t)(off + ml1) * HD + col) = o;
            }
        }
    }
}

// expert down: pair = gate * (act @ w2[e] + b2) scattered to (token,slot)
__global__ void __launch_bounds__(256)
k_mma2(const float* __restrict__ W2, const float* __restrict__ B2) {
    __shared__ __align__(16) float sA[MTILE * SROW];
    __shared__ __align__(16) float sB[NTILE * SROW];
    __shared__ float gsh[MTILE];
    __shared__ int dsh[MTILE];
    __shared__ float bsh[NTILE];
    int t = threadIdx.x;
    int bm = blockIdx.x;
    int bn = blockIdx.y;
    int e = 0;
    int acct = 0;
    int cnt = 0;
    for (; e < N_EXP; ++e) {
        cnt = g_cnt[e];
        int tiles = (cnt + MTILE - 1) / MTILE;
        if (bm < acct + tiles) break;
        acct += tiles;
    }
    if (e >= N_EXP) return;
    int off = g_off[e];
    int m0 = (bm - acct) * MTILE;
    if (t < MTILE) {
        int ml = m0 + t;
        if (ml < cnt) {
            gsh[t] = g_gate_flat[off + ml];
            dsh[t] = g_dst[off + ml];
        } else {
            gsh[t] = 0.0f;
            dsh[t] = -1;
        }
    }
    if (t < NTILE) bsh[t] = B2[e * DM + bn * NTILE + t];
    __syncthreads();
    int warp = t >> 5;
    int lane = t & 31;
    int wm = warp >> 1;
    int wn = warp & 1;
    int gid = lane >> 2;
    int tig = lane & 3;
    float acc[2][4][4] = {};
    for (int k0 = 0; k0 < HD; k0 += KS) {
        #pragma unroll
        for (int cc = 0; cc < 2; ++cc) {
            int c = t + cc * 256;
            int row = c >> 2;
            int q = c & 3;
            float4 v = make_float4(0.f, 0.f, 0.f, 0.f);
            if (m0 + row < cnt) {
                v = *(const float4*)(g_act + (size_t)(off + m0 + row) * HD + k0 + q * 4);
            }
            *(float4*)(&sA[row * SROW + q * 4]) = v;
        }
        {
            int kk = t >> 4;
            int n4 = (t & 15) << 2;
            float4 v = *(const float4*)(W2 + ((size_t)e * HD + k0 + kk) * DM + (size_t)bn * NTILE + n4);
            sB[(n4 + 0) * SROW + kk] = v.x;
            sB[(n4 + 1) * SROW + kk] = v.y;
            sB[(n4 + 2) * SROW + kk] = v.z;
            sB[(n4 + 3) * SROW + kk] = v.w;
        }
        __syncthreads();
        #pragma unroll
        for (int ks = 0; ks < 2; ++ks) {
            int kb = ks * 8;
            uint32_t bhi[4][2];
            uint32_t blo[4][2];
            #pragma unroll
            for (int nt = 0; nt < 4; ++nt) {
                int nr = wn * 32 + nt * 8 + gid;
                float v0 = sB[nr * SROW + kb + tig];
                float v1 = sB[nr * SROW + kb + tig + 4];
                uint32_t h0 = tf32_hi_bits(v0);
                uint32_t h1 = tf32_hi_bits(v1);
                bhi[nt][0] = h0;
                bhi[nt][1] = h1;
                blo[nt][0] = __float_as_uint(v0 - __uint_as_float(h0));
                blo[nt][1] = __float_as_uint(v1 - __uint_as_float(h1));
            }
            #pragma unroll
            for (int mt = 0; mt < 2; ++mt) {
                int r0 = wm * 32 + mt * 16 + gid;
                float a0f = sA[r0 * SROW + kb + tig];
                float a1f = sA[(r0 + 8) * SROW + kb + tig];
                float a2f = sA[r0 * SROW + kb + tig + 4];
                float a3f = sA[(r0 + 8) * SROW + kb + tig + 4];
                uint32_t ah0 = tf32_hi_bits(a0f);
                uint32_t ah1 = tf32_hi_bits(a1f);
                uint32_t ah2 = tf32_hi_bits(a2f);
                uint32_t ah3 = tf32_hi_bits(a3f);
                uint32_t al0 = __float_as_uint(a0f - __uint_as_float(ah0));
                uint32_t al1 = __float_as_uint(a1f - __uint_as_float(ah1));
                uint32_t al2 = __float_as_uint(a2f - __uint_as_float(ah2));
                uint32_t al3 = __float_as_uint(a3f - __uint_as_float(ah3));
                #pragma unroll
                for (int nt = 0; nt < 4; ++nt) {
                    mma_tf32(acc[mt][nt][0], acc[mt][nt][1], acc[mt][nt][2], acc[mt][nt][3],
                             ah0, ah1, ah2, ah3, bhi[nt][0], bhi[nt][1]);
                    mma_tf32(acc[mt][nt][0], acc[mt][nt][1], acc[mt][nt][2], acc[mt][nt][3],
                             ah0, ah1, ah2, ah3, blo[nt][0], blo[nt][1]);
                    mma_tf32(acc[mt][nt][0], acc[mt][nt][1], acc[mt][nt][2], acc[mt][nt][3],
                             al0, al1, al2, al3, bhi[nt][0], bhi[nt][1]);
                }
            }
        }
        __syncthreads();
    }
    #pragma unroll
    for (int mt = 0; mt < 2; ++mt) {
        int rloc0 = wm * 32 + mt * 16 + gid;
        int rloc1 = rloc0 + 8;
        int d0 = dsh[rloc0];
        int d1 = dsh[rloc1];
        float gt0 = gsh[rloc0];
        float gt1 = gsh[rloc1];
        #pragma unroll
        for (int nt = 0; nt < 4; ++nt) {
            int cl = wn * 32 + nt * 8 + tig * 2;
            int col = bn * NTILE + cl;
            float bx = bsh[cl];
            float by = bsh[cl + 1];
            if (d0 >= 0) {
                float2 o;
                o.x = gt0 * (acc[mt][nt][0] + bx);
                o.y = gt0 * (acc[mt][nt][1] + by);
                *(float2*)(g_pair + (size_t)d0 * DM + col) = o;
            }
            if (d1 >= 0) {
                float2 o;
                o.x = gt1 * (acc[mt][nt][2] + bx);
                o.y = gt1 * (acc[mt][nt][3] + by);
                *(float2*)(g_pair + (size_t)d1 * DM + col) = o;
            }
        }
    }
}

__global__ void __launch_bounds__(256)
k_final(const float* __restrict__ gm, const float* __restrict__ bmo,
        const float* __restrict__ go, const float* __restrict__ bo,
        const float* __restrict__ wc, const float* __restrict__ bc,
        float* __restrict__ out) {
    __shared__ float red[8];
    int n = blockIdx.x;
    int t = threadIdx.x;
    const float* hrow = g_h + (size_t)n * DM;
    const float* p0 = g_pair + (size_t)(n * 2 + 0) * DM;
    const float* p1 = g_pair + (size_t)(n * 2 + 1) * DM;
    float c[4];
    #pragma unroll
    for (int i = 0; i < 4; ++i) {
        int d = t + i * 256;
        c[i] = hrow[d] + p0[d] + p1[d];
    }
    float s = c[0] + c[1] + c[2] + c[3];
    float mean = block_sum256(s, red) * (1.0f / DM);
    float q = 0.0f;
    #pragma unroll
    for (int i = 0; i < 4; ++i) {
        float d = c[i] - mean;
        q += d * d;
    }
    float rstd = rsqrtf(block_sum256(q, red) * (1.0f / DM) + 1e-5f);
    float y[4];
    #pragma unroll
    for (int i = 0; i < 4; ++i) {
        int d = t + i * 256;
        y[i] = (c[i] - mean) * rstd * gm[d] + bmo[d];
    }
    float s2 = y[0] + y[1] + y[2] + y[3];
    float mean2 = block_sum256(s2, red) * (1.0f / DM);
    float q2 = 0.0f;
    #pragma unroll
    for (int i = 0; i < 4; ++i) {
        float d = y[i] - mean2;
        q2 += d * d;
    }
    float rstd2 = rsqrtf(block_sum256(q2, red) * (1.0f / DM) + 1e-5f);
    float a0 = 0.0f;
    float a1 = 0.0f;
    #pragma unroll
    for (int i = 0; i < 4; ++i) {
        int d = t + i * 256;
        float z = (y[i] - mean2) * rstd2 * go[d] + bo[d];
        a0 += z * wc[d * 2 + 0];
        a1 += z * wc[d * 2 + 1];
    }
    a0 = block_sum256(a0, red);
    a1 = block_sum256(a1, red);
    if (t == 0) {
        out[n * 2 + 0] = a0 + bc[0];
        out[n * 2 + 1] = a1 + bc[1];
    }
}

extern "C" void kernel_launch(void* const* d_in, const int* in_sizes, int n_in,
                              void* d_out, int out_size) {
    const float* x = (const float*)d_in[0];
    const float* w_in = (const float*)d_in[1];
    const float* b_in = (const float*)d_in[2];
    const float* g_in = (const float*)d_in[3];
    const float* be_in = (const float*)d_in[4];
    const float* w_g = (const float*)d_in[5];
    const float* w1 = (const float*)d_in[6];
    const float* b1 = (const float*)d_in[7];
    const float* w2 = (const float*)d_in[8];
    const float* b2 = (const float*)d_in[9];
    const float* g_mo = (const float*)d_in[10];
    const float* be_mo = (const float*)d_in[11];
    const float* g_ou = (const float*)d_in[12];
    const float* be_ou = (const float*)d_in[13];
    const float* w_c = (const float*)d_in[14];
    const float* b_c = (const float*)d_in[15];
    float* out = (float*)d_out;

    k_zero<<<1, 32>>>();
    k_gemm_in<<<dim3(N_TOK / BM, DM / BN), 256>>>(x, w_in, b_in);
    k_ln_router<<<N_TOK, 256>>>(g_in, be_in, w_g);
    k_offsets<<<1, 32>>>();
    k_scatter<<<N_TOK / 256, 256>>>();
    k_mma1<<<dim3(MT2, HD / NTILE), 256>>>(w1, b1);
    k_mma2<<<dim3(MT2, DM / NTILE), 256>>>(w2, b2);
    k_final<<<N_TOK, 256>>>(g_mo, be_mo, g_ou, be_ou, w_c, b_c, out);
}

// round 17
// speedup vs baseline: 1.8084x; 1.2321x over previous
#include <cuda_runtime.h>
#include <stdint.h>
#include <math.h>

#define N_TOK 16384
#define DIN 256
#define DM 1024
#define HD 2048
#define N_EXP 8
#define NKPAIR 32768

#define BM 64
#define BN 64
#define BK 16

#define MTILE 128
#define NTILE 64
#define KS 16
#define SROW 20            // A smem row stride (floats), conflict-free
#define SROWB 72           // B smem k-row stride (floats), conflict-free
#define MT2 ((NKPAIR / MTILE) + N_EXP)

__device__ __align__(16) float g_h[(size_t)N_TOK * DM];
__device__ __align__(16) float g_act[(size_t)NKPAIR * HD];
__device__ __align__(16) float g_pair[(size_t)NKPAIR * DM];
__device__ int g_cnt[N_EXP];
__device__ int g_cursor[N_EXP];
__device__ int g_off[N_EXP];
__device__ int g_top_idx[N_TOK * 2];
__device__ float g_top_gate[N_TOK * 2];
__device__ int g_src_tok[NKPAIR];
__device__ float g_gate_flat[NKPAIR];
__device__ int g_dst[NKPAIR];

// tf32 m16n8k8 mma, fp32 accum (sm_80 base-target), scalar b32 operands
__device__ __forceinline__ void mma_tf32(float& c0, float& c1, float& c2, float& c3,
                                         uint32_t a0, uint32_t a1, uint32_t a2, uint32_t a3,
                                         uint32_t b0, uint32_t b1) {
    asm volatile("mma.sync.aligned.m16n8k8.row.col.f32.tf32.tf32.f32 "
        "{%0,%1,%2,%3}, {%4,%5,%6,%7}, {%8,%9}, {%0,%1,%2,%3};"
        : "+f"(c0), "+f"(c1), "+f"(c2), "+f"(c3)
        : "r"(a0), "r"(a1), "r"(a2), "r"(a3), "r"(b0), "r"(b1));
}

__device__ __forceinline__ uint32_t tf32_hi_bits(float v) {
    return __float_as_uint(v) & 0xFFFFE000u;
}

__device__ __forceinline__ uint32_t smem_u32(const void* p) {
    uint32_t a;
    asm("{ .reg .u64 t; cvta.to.shared.u64 t, %1; cvt.u32.u64 %0, t; }"
        : "=r"(a) : "l"(p));
    return a;
}
// async copy of 16 bytes; srcsz = 16 normal, 0 -> zero-fill destination
__device__ __forceinline__ void cpa16(uint32_t saddr, const void* g, uint32_t srcsz) {
    asm volatile("cp.async.ca.shared.global [%0], [%1], 16, %2;"
                 :: "r"(saddr), "l"(g), "r"(srcsz));
}
__device__ __forceinline__ void cpa_commit() {
    asm volatile("cp.async.commit_group;");
}
__device__ __forceinline__ void cpa_wait1() {
    asm volatile("cp.async.wait_group 1;");
}
__device__ __forceinline__ void cpa_wait0() {
    asm volatile("cp.async.wait_group 0;");
}

__device__ __forceinline__ float block_sum256(float v, float* red) {
    #pragma unroll
    for (int o = 16; o > 0; o = o >> 1) {
        v += __shfl_xor_sync(0xffffffffu, v, o);
    }
    __syncthreads();
    if ((threadIdx.x & 31) == 0) red[threadIdx.x >> 5] = v;
    __syncthreads();
    float s = 0.0f;
    #pragma unroll
    for (int i = 0; i < 8; ++i) s += red[i];
    return s;
}

__device__ __forceinline__ float gelu_tanh(float x) {
    float x3 = x * x * x;
    float u = 0.7978845608028654f * (x + 0.044715f * x3);
    return 0.5f * x * (1.0f + tanhf(u));
}

__global__ void k_zero() {
    int t = threadIdx.x;
    if (t < N_EXP) {
        g_cnt[t] = 0;
        g_cursor[t] = 0;
    }
}

__global__ void __launch_bounds__(256)
k_gemm_in(const float* __restrict__ X, const float* __restrict__ W,
          const float* __restrict__ bias) {
    __shared__ __align__(16) float As[BK][BM];
    __shared__ __align__(16) float Bs[BK][BN];
    __shared__ float bsh[BN];
    int t = threadIdx.x;
    int m0 = blockIdx.x * BM;
    int n0 = blockIdx.y * BN;
    if (t < BN) bsh[t] = bias[n0 + t];
    int la_m = t >> 2;
    int la_k = (t & 3) << 2;
    int lb_k = t >> 4;
    int lb_n = (t & 15) << 2;
    int tx = (t & 15) << 2;
    int ty = (t >> 4) << 2;
    float acc[4][4] = {};
    for (int k0 = 0; k0 < DIN; k0 += BK) {
        float4 av = *(const float4*)(X + (size_t)(m0 + la_m) * DIN + k0 + la_k);
        As[la_k + 0][la_m] = av.x;
        As[la_k + 1][la_m] = av.y;
        As[la_k + 2][la_m] = av.z;
        As[la_k + 3][la_m] = av.w;
        *(float4*)(&Bs[lb_k][lb_n]) = *(const float4*)(W + (size_t)(k0 + lb_k) * DM + n0 + lb_n);
        __syncthreads();
        #pragma unroll
        for (int kk = 0; kk < BK; ++kk) {
            float4 a = *(const float4*)(&As[kk][ty]);
            float4 b = *(const float4*)(&Bs[kk][tx]);
            acc[0][0] += a.x * b.x; acc[0][1] += a.x * b.y; acc[0][2] += a.x * b.z; acc[0][3] += a.x * b.w;
            acc[1][0] += a.y * b.x; acc[1][1] += a.y * b.y; acc[1][2] += a.y * b.z; acc[1][3] += a.y * b.w;
            acc[2][0] += a.z * b.x; acc[2][1] += a.z * b.y; acc[2][2] += a.z * b.z; acc[2][3] += a.z * b.w;
            acc[3][0] += a.w * b.x; acc[3][1] += a.w * b.y; acc[3][2] += a.w * b.z; acc[3][3] += a.w * b.w;
        }
        __syncthreads();
    }
    float4 bv = *(const float4*)(&bsh[tx]);
    #pragma unroll
    for (int i = 0; i < 4; ++i) {
        float4 o;
        o.x = acc[i][0] + bv.x;
        o.y = acc[i][1] + bv.y;
        o.z = acc[i][2] + bv.z;
        o.w = acc[i][3] + bv.w;
        *(float4*)(g_h + (size_t)(m0 + ty + i) * DM + n0 + tx) = o;
    }
}

__global__ void __launch_bounds__(256)
k_ln_router(const float* __restrict__ gw, const float* __restrict__ gb,
            const float* __restrict__ wg) {
    __shared__ float red[8];
    __shared__ float pbuf[256][9];
    __shared__ float lg[N_EXP];
    int n = blockIdx.x;
    int t = threadIdx.x;
    float* row = g_h + (size_t)n * DM;
    float v[4];
    #pragma unroll
    for (int i = 0; i < 4; ++i) v[i] = row[t + i * 256];
    float s = v[0] + v[1] + v[2] + v[3];
    float mean = block_sum256(s, red) * (1.0f / DM);
    float q = 0.0f;
    #pragma unroll
    for (int i = 0; i < 4; ++i) {
        float d = v[i] - mean;
        q += d * d;
    }
    float var = block_sum256(q, red) * (1.0f / DM);
    float rstd = rsqrtf(var + 1e-5f);
    float pl[N_EXP] = {};
    #pragma unroll
    for (int i = 0; i < 4; ++i) {
        int d = t + i * 256;
        float hn = (v[i] - mean) * rstd * gw[d] + gb[d];
        row[d] = hn;
        const float* wr = wg + (size_t)d * N_EXP;
        #pragma unroll
        for (int e = 0; e < N_EXP; ++e) pl[e] += hn * wr[e];
    }
    #pragma unroll
    for (int e = 0; e < N_EXP; ++e) pbuf[t][e] = pl[e];
    __syncthreads();
    int w = t >> 5;
    int l = t & 31;
    float ls = 0.0f;
    #pragma unroll
    for (int j = 0; j < 8; ++j) ls += pbuf[l + j * 32][w];
    #pragma unroll
    for (int o = 16; o > 0; o = o >> 1) {
        ls += __shfl_xor_sync(0xffffffffu, ls, o);
    }
    if (l == 0) lg[w] = ls;
    __syncthreads();
    if (t == 0) {
        float m = lg[0];
        #pragma unroll
        for (int e = 1; e < N_EXP; ++e) m = fmaxf(m, lg[e]);
        float ex[N_EXP];
        float Z = 0.0f;
        #pragma unroll
        for (int e = 0; e < N_EXP; ++e) {
            ex[e] = expf(lg[e] - m);
            Z += ex[e];
        }
        int i0 = 0;
        float p0 = ex[0];
        #pragma unroll
        for (int e = 1; e < N_EXP; ++e) {
            if (ex[e] > p0) {
                p0 = ex[e];
                i0 = e;
            }
        }
        int i1 = -1;
        float p1 = -1.0f;
        #pragma unroll
        for (int e = 0; e < N_EXP; ++e) {
            if (e != i0 && ex[e] > p1) {
                p1 = ex[e];
                i1 = e;
            }
        }
        float pa = p0 / Z;
        float pb = p1 / Z;
        float ss = pa + pb + 1e-9f;
        g_top_idx[n * 2 + 0] = i0;
        g_top_idx[n * 2 + 1] = i1;
        g_top_gate[n * 2 + 0] = pa / ss;
        g_top_gate[n * 2 + 1] = pb / ss;
        atomicAdd(&g_cnt[i0], 1);
        atomicAdd(&g_cnt[i1], 1);
    }
}

__global__ void k_offsets() {
    if (threadIdx.x == 0) {
        int a = 0;
        #pragma unroll
        for (int e = 0; e < N_EXP; ++e) {
            g_off[e] = a;
            a += g_cnt[e];
        }
    }
}

__global__ void k_scatter() {
    int n = blockIdx.x * blockDim.x + threadIdx.x;
    if (n >= N_TOK) return;
    #pragma unroll
    for (int s = 0; s < 2; ++s) {
        int e = g_top_idx[n * 2 + s];
        int pos = atomicAdd(&g_cursor[e], 1);
        int f = g_off[e] + pos;
        g_src_tok[f] = n;
        g_gate_flat[f] = g_top_gate[n * 2 + s];
        g_dst[f] = n * 2 + s;
    }
}

// expert up: act = gelu(gather(h) @ w1[e] + b1), tf32 3-term split mma,
// 2-stage cp.async pipeline. Block 128x64, 8 warps (4x2), 32x32 per warp.
__global__ void __launch_bounds__(256)
k_mma1(const float* __restrict__ W1, const float* __restrict__ B1) {
    __shared__ __align__(16) float sA[2][MTILE * SROW];
    __shared__ __align__(16) float sB[2][KS * SROWB];
    __shared__ int toks[MTILE];
    __shared__ float bsh[NTILE];
    int t = threadIdx.x;
    int bm = blockIdx.x;
    int bn = blockIdx.y;
    int e = 0;
    int acct = 0;
    int cnt = 0;
    for (; e < N_EXP; ++e) {
        cnt = g_cnt[e];
        int tiles = (cnt + MTILE - 1) / MTILE;
        if (bm < acct + tiles) break;
        acct += tiles;
    }
    if (e >= N_EXP) return;
    int off = g_off[e];
    int m0 = (bm - acct) * MTILE;
    if (t < MTILE) {
        int ml = m0 + t;
        toks[t] = (ml < cnt) ? g_src_tok[off + ml] : -1;
    }
    if (t < NTILE) bsh[t] = B1[e * HD + bn * NTILE + t];
    __syncthreads();
    int warp = t >> 5;
    int lane = t & 31;
    int wm = warp >> 1;
    int wn = warp & 1;
    int gid = lane >> 2;
    int tig = lane & 3;
    // per-thread fill coordinates
    int ar0 = t >> 2;              // A chunk rows (2 per thread)
    int aq0 = (t & 3) << 2;
    int tokA0 = toks[ar0];
    int ar1 = (t + 256) >> 2;
    int tokA1 = toks[ar1];
    int bkk = t >> 4;              // B: k-row
    int bn4 = (t & 15) << 2;       // B: n offset
    const float* wbase = W1 + (size_t)e * DM * HD + (size_t)bn * NTILE;
    // prefetch slab 0
    {
        int k0 = 0;
        cpa16(smem_u32(&sA[0][ar0 * SROW + aq0]),
              tokA0 >= 0 ? (g_h + (size_t)tokA0 * DM + k0 + aq0) : g_h,
              tokA0 >= 0 ? 16u : 0u);
        cpa16(smem_u32(&sA[0][ar1 * SROW + aq0]),
              tokA1 >= 0 ? (g_h + (size_t)tokA1 * DM + k0 + aq0) : g_h,
              tokA1 >= 0 ? 16u : 0u);
        cpa16(smem_u32(&sB[0][bkk * SROWB + bn4]),
              wbase + (size_t)(k0 + bkk) * HD + bn4, 16u);
        cpa_commit();
    }
    float acc[2][4][4] = {};
    int S = DM / KS;
    for (int s = 0; s < S; ++s) {
        int cur = s & 1;
        if (s + 1 < S) {
            int k0 = (s + 1) * KS;
            int nxt = cur ^ 1;
            cpa16(smem_u32(&sA[nxt][ar0 * SROW + aq0]),
                  tokA0 >= 0 ? (g_h + (size_t)tokA0 * DM + k0 + aq0) : g_h,
                  tokA0 >= 0 ? 16u : 0u);
            cpa16(smem_u32(&sA[nxt][ar1 * SROW + aq0]),
                  tokA1 >= 0 ? (g_h + (size_t)tokA1 * DM + k0 + aq0) : g_h,
                  tokA1 >= 0 ? 16u : 0u);
            cpa16(smem_u32(&sB[nxt][bkk * SROWB + bn4]),
                  wbase + (size_t)(k0 + bkk) * HD + bn4, 16u);
            cpa_commit();
            cpa_wait1();
        } else {
            cpa_wait0();
        }
        __syncthreads();
        #pragma unroll
        for (int ks = 0; ks < 2; ++ks) {
            int kb = ks * 8;
            uint32_t bhi[4][2];
            uint32_t blo[4][2];
            #pragma unroll
            for (int nt = 0; nt < 4; ++nt) {
                int nr = wn * 32 + nt * 8 + gid;
                float v0 = sB[cur][(kb + tig) * SROWB + nr];
                float v1 = sB[cur][(kb + tig + 4) * SROWB + nr];
                uint32_t h0 = tf32_hi_bits(v0);
                uint32_t h1 = tf32_hi_bits(v1);
                bhi[nt][0] = h0;
                bhi[nt][1] = h1;
                blo[nt][0] = __float_as_uint(v0 - __uint_as_float(h0));
                blo[nt][1] = __float_as_uint(v1 - __uint_as_float(h1));
            }
            #pragma unroll
            for (int mt = 0; mt < 2; ++mt) {
                int r0 = wm * 32 + mt * 16 + gid;
                float a0f = sA[cur][r0 * SROW + kb + tig];
                float a1f = sA[cur][(r0 + 8) * SROW + kb + tig];
                float a2f = sA[cur][r0 * SROW + kb + tig + 4];
                float a3f = sA[cur][(r0 + 8) * SROW + kb + tig + 4];
                uint32_t ah0 = tf32_hi_bits(a0f);
                uint32_t ah1 = tf32_hi_bits(a1f);
                uint32_t ah2 = tf32_hi_bits(a2f);
                uint32_t ah3 = tf32_hi_bits(a3f);
                uint32_t al0 = __float_as_uint(a0f - __uint_as_float(ah0));
                uint32_t al1 = __float_as_uint(a1f - __uint_as_float(ah1));
                uint32_t al2 = __float_as_uint(a2f - __uint_as_float(ah2));
                uint32_t al3 = __float_as_uint(a3f - __uint_as_float(ah3));
                #pragma unroll
                for (int nt = 0; nt < 4; ++nt) {
                    mma_tf32(acc[mt][nt][0], acc[mt][nt][1], acc[mt][nt][2], acc[mt][nt][3],
                             ah0, ah1, ah2, ah3, bhi[nt][0], bhi[nt][1]);
                    mma_tf32(acc[mt][nt][0], acc[mt][nt][1], acc[mt][nt][2], acc[mt][nt][3],
                             ah0, ah1, ah2, ah3, blo[nt][0], blo[nt][1]);
                    mma_tf32(acc[mt][nt][0], acc[mt][nt][1], acc[mt][nt][2], acc[mt][nt][3],
                             al0, al1, al2, al3, bhi[nt][0], bhi[nt][1]);
                }
            }
        }
        __syncthreads();
    }
    #pragma unroll
    for (int mt = 0; mt < 2; ++mt) {
        int rloc0 = wm * 32 + mt * 16 + gid;
        int rloc1 = rloc0 + 8;
        int ml0 = m0 + rloc0;
        int ml1 = m0 + rloc1;
        #pragma unroll
        for (int nt = 0; nt < 4; ++nt) {
            int cl = wn * 32 + nt * 8 + tig * 2;
            int col = bn * NTILE + cl;
            float bx = bsh[cl];
            float by = bsh[cl + 1];
            if (ml0 < cnt) {
                float2 o;
                o.x = gelu_tanh(acc[mt][nt][0] + bx);
                o.y = gelu_tanh(acc[mt][nt][1] + by);
                *(float2*)(g_act + (size_t)(off + ml0) * HD + col) = o;
            }
            if (ml1 < cnt) {
                float2 o;
                o.x = gelu_tanh(acc[mt][nt][2] + bx);
                o.y = gelu_tanh(acc[mt][nt][3] + by);
                *(float2*)(g_act + (size_t)(off + ml1) * HD + col) = o;
            }
        }
    }
}

// expert down: pair = gate * (act @ w2[e] + b2) scattered to (token,slot)
__global__ void __launch_bounds__(256)
k_mma2(const float* __restrict__ W2, const float* __restrict__ B2) {
    __shared__ __align__(16) float sA[2][MTILE * SROW];
    __shared__ __align__(16) float sB[2][KS * SROWB];
    __shared__ float gsh[MTILE];
    __shared__ int dsh[MTILE];
    __shared__ float bsh[NTILE];
    int t = threadIdx.x;
    int bm = blockIdx.x;
    int bn = blockIdx.y;
    int e = 0;
    int acct = 0;
    int cnt = 0;
    for (; e < N_EXP; ++e) {
        cnt = g_cnt[e];
        int tiles = (cnt + MTILE - 1) / MTILE;
        if (bm < acct + tiles) break;
        acct += tiles;
    }
    if (e >= N_EXP) return;
    int off = g_off[e];
    int m0 = (bm - acct) * MTILE;
    if (t < MTILE) {
        int ml = m0 + t;
        if (ml < cnt) {
            gsh[t] = g_gate_flat[off + ml];
            dsh[t] = g_dst[off + ml];
        } else {
            gsh[t] = 0.0f;
            dsh[t] = -1;
        }
    }
    if (t < NTILE) bsh[t] = B2[e * DM + bn * NTILE + t];
    __syncthreads();
    int warp = t >> 5;
    int lane = t & 31;
    int wm = warp >> 1;
    int wn = warp & 1;
    int gid = lane >> 2;
    int tig = lane & 3;
    int ar0 = t >> 2;
    int aq0 = (t & 3) << 2;
    int ok0 = (m0 + ar0) < cnt;
    int ar1 = (t + 256) >> 2;
    int ok1 = (m0 + ar1) < cnt;
    int bkk = t >> 4;
    int bn4 = (t & 15) << 2;
    const float* wbase = W2 + (size_t)e * HD * DM + (size_t)bn * NTILE;
    const float* a0base = g_act + (size_t)(off + m0 + ar0) * HD + aq0;
    const float* a1base = g_act + (size_t)(off + m0 + ar1) * HD + aq0;
    {
        cpa16(smem_u32(&sA[0][ar0 * SROW + aq0]), ok0 ? a0base : g_act, ok0 ? 16u : 0u);
        cpa16(smem_u32(&sA[0][ar1 * SROW + aq0]), ok1 ? a1base : g_act, ok1 ? 16u : 0u);
        cpa16(smem_u32(&sB[0][bkk * SROWB + bn4]), wbase + (size_t)bkk * DM + bn4, 16u);
        cpa_commit();
    }
    float acc[2][4][4] = {};
    int S = HD / KS;
    for (int s = 0; s < S; ++s) {
        int cur = s & 1;
        if (s + 1 < S) {
            int k0 = (s + 1) * KS;
            int nxt = cur ^ 1;
            cpa16(smem_u32(&sA[nxt][ar0 * SROW + aq0]), ok0 ? (a0base + k0) : g_act, ok0 ? 16u : 0u);
            cpa16(smem_u32(&sA[nxt][ar1 * SROW + aq0]), ok1 ? (a1base + k0) : g_act, ok1 ? 16u : 0u);
            cpa16(smem_u32(&sB[nxt][bkk * SROWB + bn4]), wbase + (size_t)(k0 + bkk) * DM + bn4, 16u);
            cpa_commit();
            cpa_wait1();
        } else {
            cpa_wait0();
        }
        __syncthreads();
        #pragma unroll
        for (int ks = 0; ks < 2; ++ks) {
            int kb = ks * 8;
            uint32_t bhi[4][2];
            uint32_t blo[4][2];
            #pragma unroll
            for (int nt = 0; nt < 4; ++nt) {
                int nr = wn * 32 + nt * 8 + gid;
                float v0 = sB[cur][(kb + tig) * SROWB + nr];
                float v1 = sB[cur][(kb + tig + 4) * SROWB + nr];
                uint32_t h0 = tf32_hi_bits(v0);
                uint32_t h1 = tf32_hi_bits(v1);
                bhi[nt][0] = h0;
                bhi[nt][1] = h1;
                blo[nt][0] = __float_as_uint(v0 - __uint_as_float(h0));
                blo[nt][1] = __float_as_uint(v1 - __uint_as_float(h1));
            }
            #pragma unroll
            for (int mt = 0; mt < 2; ++mt) {
                int r0 = wm * 32 + mt * 16 + gid;
                float a0f = sA[cur][r0 * SROW + kb + tig];
                float a1f = sA[cur][(r0 + 8) * SROW + kb + tig];
                float a2f = sA[cur][r0 * SROW + kb + tig + 4];
                float a3f = sA[cur][(r0 + 8) * SROW + kb + tig + 4];
                uint32_t ah0 = tf32_hi_bits(a0f);
                uint32_t ah1 = tf32_hi_bits(a1f);
                uint32_t ah2 = tf32_hi_bits(a2f);
                uint32_t ah3 = tf32_hi_bits(a3f);
                uint32_t al0 = __float_as_uint(a0f - __uint_as_float(ah0));
                uint32_t al1 = __float_as_uint(a1f - __uint_as_float(ah1));
                uint32_t al2 = __float_as_uint(a2f - __uint_as_float(ah2));
                uint32_t al3 = __float_as_uint(a3f - __uint_as_float(ah3));
                #pragma unroll
                for (int nt = 0; nt < 4; ++nt) {
                    mma_tf32(acc[mt][nt][0], acc[mt][nt][1], acc[mt][nt][2], acc[mt][nt][3],
                             ah0, ah1, ah2, ah3, bhi[nt][0], bhi[nt][1]);
                    mma_tf32(acc[mt][nt][0], acc[mt][nt][1], acc[mt][nt][2], acc[mt][nt][3],
                             ah0, ah1, ah2, ah3, blo[nt][0], blo[nt][1]);
                    mma_tf32(acc[mt][nt][0], acc[mt][nt][1], acc[mt][nt][2], acc[mt][nt][3],
                             al0, al1, al2, al3, bhi[nt][0], bhi[nt][1]);
                }
            }
        }
        __syncthreads();
    }
    #pragma unroll
    for (int mt = 0; mt < 2; ++mt) {
        int rloc0 = wm * 32 + mt * 16 + gid;
        int rloc1 = rloc0 + 8;
        int d0 = dsh[rloc0];
        int d1 = dsh[rloc1];
        float gt0 = gsh[rloc0];
        float gt1 = gsh[rloc1];
        #pragma unroll
        for (int nt = 0; nt < 4; ++nt) {
            int cl = wn * 32 + nt * 8 + tig * 2;
            int col = bn * NTILE + cl;
            float bx = bsh[cl];
            float by = bsh[cl + 1];
            if (d0 >= 0) {
                float2 o;
                o.x = gt0 * (acc[mt][nt][0] + bx);
                o.y = gt0 * (acc[mt][nt][1] + by);
                *(float2*)(g_pair + (size_t)d0 * DM + col) = o;
            }
            if (d1 >= 0) {
                float2 o;
                o.x = gt1 * (acc[mt][nt][2] + bx);
                o.y = gt1 * (acc[mt][nt][3] + by);
                *(float2*)(g_pair + (size_t)d1 * DM + col) = o;
            }
        }
    }
}

__global__ void __launch_bounds__(256)
k_final(const float* __restrict__ gm, const float* __restrict__ bmo,
        const float* __restrict__ go, const float* __restrict__ bo,
        const float* __restrict__ wc, const float* __restrict__ bc,
        float* __restrict__ out) {
    __shared__ float red[8];
    int n = blockIdx.x;
    int t = threadIdx.x;
    const float* hrow = g_h + (size_t)n * DM;
    const float* p0 = g_pair + (size_t)(n * 2 + 0) * DM;
    const float* p1 = g_pair + (size_t)(n * 2 + 1) * DM;
    float c[4];
    #pragma unroll
    for (int i = 0; i < 4; ++i) {
        int d = t + i * 256;
        c[i] = hrow[d] + p0[d] + p1[d];
    }
    float s = c[0] + c[1] + c[2] + c[3];
    float mean = block_sum256(s, red) * (1.0f / DM);
    float q = 0.0f;
    #pragma unroll
    for (int i = 0; i < 4; ++i) {
        float d = c[i] - mean;
        q += d * d;
    }
    float rstd = rsqrtf(block_sum256(q, red) * (1.0f / DM) + 1e-5f);
    float y[4];
    #pragma unroll
    for (int i = 0; i < 4; ++i) {
        int d = t + i * 256;
        y[i] = (c[i] - mean) * rstd * gm[d] + bmo[d];
    }
    float s2 = y[0] + y[1] + y[2] + y[3];
    float mean2 = block_sum256(s2, red) * (1.0f / DM);
    float q2 = 0.0f;
    #pragma unroll
    for (int i = 0; i < 4; ++i) {
        float d = y[i] - mean2;
        q2 += d * d;
    }
    float rstd2 = rsqrtf(block_sum256(q2, red) * (1.0f / DM) + 1e-5f);
    float a0 = 0.0f;
    float a1 = 0.0f;
    #pragma unroll
    for (int i = 0; i < 4; ++i) {
        int d = t + i * 256;
        float z = (y[i] - mean2) * rstd2 * go[d] + bo[d];
        a0 += z * wc[d * 2 + 0];
        a1 += z * wc[d * 2 + 1];
    }
    a0 = block_sum256(a0, red);
    a1 = block_sum256(a1, red);
    if (t == 0) {
        out[n * 2 + 0] = a0 + bc[0];
        out[n * 2 + 1] = a1 + bc[1];
    }
}

extern "C" void kernel_launch(void* const* d_in, const int* in_sizes, int n_in,
                              void* d_out, int out_size) {
    const float* x = (const float*)d_in[0];
    const float* w_in = (const float*)d_in[1];
    const float* b_in = (const float*)d_in[2];
    const float* g_in = (const float*)d_in[3];
    const float* be_in = (const float*)d_in[4];
    const float* w_g = (const float*)d_in[5];
    const float* w1 = (const float*)d_in[6];
    const float* b1 = (const float*)d_in[7];
    const float* w2 = (const float*)d_in[8];
    const float* b2 = (const float*)d_in[9];
    const float* g_mo = (const float*)d_in[10];
    const float* be_mo = (const float*)d_in[11];
    const float* g_ou = (const float*)d_in[12];
    const float* be_ou = (const float*)d_in[13];
    const float* w_c = (const float*)d_in[14];
    const float* b_c = (const float*)d_in[15];
    float* out = (float*)d_out;

    k_zero<<<1, 32>>>();
    k_gemm_in<<<dim3(N_TOK / BM, DM / BN), 256>>>(x, w_in, b_in);
    k_ln_router<<<N_TOK, 256>>>(g_in, be_in, w_g);
    k_offsets<<<1, 32>>>();
    k_scatter<<<N_TOK / 256, 256>>>();
    k_mma1<<<dim3(MT2, HD / NTILE), 256>>>(w1, b1);
    k_mma2<<<dim3(MT2, DM / NTILE), 256>>>(w2, b2);
    k_final<<<N_TOK, 256>>>(g_mo, be_mo, g_ou, be_ou, w_c, b_c, out);
}